// round 7
// baseline (speedup 1.0000x reference)
#include <cuda_runtime.h>
#include <cuda_bf16.h>

static const int NN = 200000;
static const int NE = 3200000;
static const int NG = 400;
static const int NB = (NN + 1023) / 1024;  // 196 scan blocks

// Scratch (device globals; no runtime allocation allowed)
__device__ int   g_degi[NN];
__device__ int   g_off[NN + 1];
__device__ int   g_cursor[NN];
__device__ int   g_csr[NE];
__device__ int   g_bsum[256];
__device__ float g_bufA[(size_t)NN * 128];  // layer outputs (max 128)
__device__ float g_bufB[(size_t)NN * 48];
__device__ float g_s0[(size_t)NN * 128];    // layer-0 self projection
__device__ float g_z[(size_t)NN * 48];      // projected neighbor features
__device__ float g_s[(size_t)NN * 48];      // self-projection + bias
__device__ float g_agg[(size_t)NN * 48];    // normalized aggregate scratch
__device__ float g_cnt[NG];

// ---------------------------------------------------------------------------
__global__ void k_degree(const int* __restrict__ dst) {
    int e = blockIdx.x * blockDim.x + threadIdx.x;
    if (e < NE) atomicAdd(&g_degi[dst[e]], 1);
}

// ---- parallel exclusive scan of g_degi -> g_off ----
__global__ void k_scan1() {
    __shared__ int sh[1024];
    int t = threadIdx.x;
    int j = blockIdx.x * 1024 + t;
    sh[t] = (j < NN) ? g_degi[j] : 0;
    __syncthreads();
    for (int d = 512; d > 0; d >>= 1) {
        if (t < d) sh[t] += sh[t + d];
        __syncthreads();
    }
    if (t == 0) g_bsum[blockIdx.x] = sh[0];
}

__global__ void k_scan2() {
    __shared__ int sh[256];
    int t = threadIdx.x;
    int v = (t < NB) ? g_bsum[t] : 0;
    sh[t] = v;
    __syncthreads();
    for (int d = 1; d < 256; d <<= 1) {
        int x = (t >= d) ? sh[t - d] : 0;
        __syncthreads();
        sh[t] += x;
        __syncthreads();
    }
    g_bsum[t] = sh[t] - v;  // exclusive
}

__global__ void k_scan3() {
    __shared__ int sh[1024];
    int t = threadIdx.x;
    int j = blockIdx.x * 1024 + t;
    int v = (j < NN) ? g_degi[j] : 0;
    sh[t] = v;
    __syncthreads();
    for (int d = 1; d < 1024; d <<= 1) {
        int x = (t >= d) ? sh[t - d] : 0;
        __syncthreads();
        sh[t] += x;
        __syncthreads();
    }
    int excl = sh[t] - v + g_bsum[blockIdx.x];
    if (j < NN) {
        g_off[j] = excl;
        g_cursor[j] = excl;
    }
    if (j == NN - 1) g_off[NN] = excl + v;
}

__global__ void k_build(const int* __restrict__ src, const int* __restrict__ dst) {
    int e = blockIdx.x * blockDim.x + threadIdx.x;
    if (e >= NE) return;
    int p = atomicAdd(&g_cursor[dst[e]], 1);
    g_csr[p] = src[e];
}

// ---------------------------------------------------------------------------
// plain gather: agg[v] = sum z[nbr] / max(deg,1)
template <int DIM, int SLOTS>
__global__ void k_gather4(const float* __restrict__ z, float* __restrict__ agg) {
    constexpr int F4L = 32 / SLOTS;
    constexpr int NF4 = DIM / 4;
    int gt = blockIdx.x * blockDim.x + threadIdx.x;
    int v = gt >> 5;
    if (v >= NN) return;
    int lane = gt & 31;
    int slot = lane / F4L;
    int f4 = lane % F4L;
    bool act = (f4 < NF4);

    int beg = g_off[v];
    int end = g_off[v + 1];
    float4 acc = make_float4(0.f, 0.f, 0.f, 0.f);

    int e = beg;
    for (; e + 4 * SLOTS <= end; e += 4 * SLOTS) {
        int s0 = g_csr[e + slot];
        int s1 = g_csr[e + SLOTS + slot];
        int s2 = g_csr[e + 2 * SLOTS + slot];
        int s3 = g_csr[e + 3 * SLOTS + slot];
        if (act) {
            float4 t0 = __ldg(reinterpret_cast<const float4*>(z + (size_t)s0 * DIM) + f4);
            float4 t1 = __ldg(reinterpret_cast<const float4*>(z + (size_t)s1 * DIM) + f4);
            float4 t2 = __ldg(reinterpret_cast<const float4*>(z + (size_t)s2 * DIM) + f4);
            float4 t3 = __ldg(reinterpret_cast<const float4*>(z + (size_t)s3 * DIM) + f4);
            acc.x += (t0.x + t1.x) + (t2.x + t3.x);
            acc.y += (t0.y + t1.y) + (t2.y + t3.y);
            acc.z += (t0.z + t1.z) + (t2.z + t3.z);
            acc.w += (t0.w + t1.w) + (t2.w + t3.w);
        }
    }
    for (; e < end; e += SLOTS) {
        int myE = e + slot;
        if (myE < end && act) {
            int s0 = g_csr[myE];
            float4 t0 = __ldg(reinterpret_cast<const float4*>(z + (size_t)s0 * DIM) + f4);
            acc.x += t0.x; acc.y += t0.y; acc.z += t0.z; acc.w += t0.w;
        }
    }
#pragma unroll
    for (int m = F4L; m < 32; m <<= 1) {
        acc.x += __shfl_xor_sync(0xFFFFFFFFu, acc.x, m);
        acc.y += __shfl_xor_sync(0xFFFFFFFFu, acc.y, m);
        acc.z += __shfl_xor_sync(0xFFFFFFFFu, acc.z, m);
        acc.w += __shfl_xor_sync(0xFFFFFFFFu, acc.w, m);
    }
    float inv = 1.0f / fmaxf((float)(end - beg), 1.0f);
    if (slot == 0 && act) {
        float4 o = make_float4(acc.x * inv, acc.y * inv, acc.z * inv, acc.w * inv);
        reinterpret_cast<float4*>(agg + (size_t)v * DIM)[f4] = o;
    }
}

// fused gather (layer 2): out[v] = relu( s[v] + sum z[nbr]/max(deg,1) )
template <int DIM, int SLOTS, bool RELU>
__global__ void k_gatherF(const float* __restrict__ z, const float* __restrict__ s,
                          float* __restrict__ out) {
    constexpr int F4L = 32 / SLOTS;
    constexpr int NF4 = DIM / 4;
    int gt = blockIdx.x * blockDim.x + threadIdx.x;
    int v = gt >> 5;
    if (v >= NN) return;
    int lane = gt & 31;
    int slot = lane / F4L;
    int f4 = lane % F4L;
    bool act = (f4 < NF4);

    int beg = g_off[v];
    int end = g_off[v + 1];
    float4 acc = make_float4(0.f, 0.f, 0.f, 0.f);

    int e = beg;
    for (; e + 4 * SLOTS <= end; e += 4 * SLOTS) {
        int s0 = g_csr[e + slot];
        int s1 = g_csr[e + SLOTS + slot];
        int s2 = g_csr[e + 2 * SLOTS + slot];
        int s3 = g_csr[e + 3 * SLOTS + slot];
        if (act) {
            float4 t0 = __ldg(reinterpret_cast<const float4*>(z + (size_t)s0 * DIM) + f4);
            float4 t1 = __ldg(reinterpret_cast<const float4*>(z + (size_t)s1 * DIM) + f4);
            float4 t2 = __ldg(reinterpret_cast<const float4*>(z + (size_t)s2 * DIM) + f4);
            float4 t3 = __ldg(reinterpret_cast<const float4*>(z + (size_t)s3 * DIM) + f4);
            acc.x += (t0.x + t1.x) + (t2.x + t3.x);
            acc.y += (t0.y + t1.y) + (t2.y + t3.y);
            acc.z += (t0.z + t1.z) + (t2.z + t3.z);
            acc.w += (t0.w + t1.w) + (t2.w + t3.w);
        }
    }
    for (; e < end; e += SLOTS) {
        int myE = e + slot;
        if (myE < end && act) {
            int s0 = g_csr[myE];
            float4 t0 = __ldg(reinterpret_cast<const float4*>(z + (size_t)s0 * DIM) + f4);
            acc.x += t0.x; acc.y += t0.y; acc.z += t0.z; acc.w += t0.w;
        }
    }
#pragma unroll
    for (int m = F4L; m < 32; m <<= 1) {
        acc.x += __shfl_xor_sync(0xFFFFFFFFu, acc.x, m);
        acc.y += __shfl_xor_sync(0xFFFFFFFFu, acc.y, m);
        acc.z += __shfl_xor_sync(0xFFFFFFFFu, acc.z, m);
        acc.w += __shfl_xor_sync(0xFFFFFFFFu, acc.w, m);
    }
    float inv = 1.0f / fmaxf((float)(end - beg), 1.0f);
    if (slot == 0 && act) {
        float4 sv = __ldg(reinterpret_cast<const float4*>(s + (size_t)v * DIM) + f4);
        float4 o = make_float4(sv.x + acc.x * inv, sv.y + acc.y * inv,
                               sv.z + acc.z * inv, sv.w + acc.w * inv);
        if (RELU) {
            o.x = fmaxf(o.x, 0.f); o.y = fmaxf(o.y, 0.f);
            o.z = fmaxf(o.z, 0.f); o.w = fmaxf(o.w, 0.f);
        }
        reinterpret_cast<float4*>(out + (size_t)v * DIM)[f4] = o;
    }
}

// fused scalar gather for DIM=5 (layer 3, no relu)
__global__ void k_gatherF5(const float* __restrict__ z, const float* __restrict__ s,
                           float* __restrict__ out) {
    constexpr int DIM = 5;
    int gt = blockIdx.x * blockDim.x + threadIdx.x;
    int v = gt >> 5;
    if (v >= NN) return;
    int lane = gt & 31;
    int slot = lane >> 3;
    int f = lane & 7;
    bool act = (f < DIM);

    int beg = g_off[v];
    int end = g_off[v + 1];
    float acc = 0.0f;
    int e = beg;
    for (; e + 8 <= end; e += 8) {
        int s0 = g_csr[e + slot];
        int s1 = g_csr[e + 4 + slot];
        if (act) acc += z[(size_t)s0 * DIM + f] + z[(size_t)s1 * DIM + f];
    }
    for (; e < end; e += 4) {
        int myE = e + slot;
        if (myE < end && act) acc += z[(size_t)g_csr[myE] * DIM + f];
    }
#pragma unroll
    for (int m = 8; m < 32; m <<= 1) acc += __shfl_xor_sync(0xFFFFFFFFu, acc, m);
    float inv = 1.0f / fmaxf((float)(end - beg), 1.0f);
    if (slot == 0 && act)
        out[(size_t)v * DIM + f] = s[(size_t)v * DIM + f] + acc * inv;
}

// ---------------------------------------------------------------------------
// General register-tiled projection: out = act( h@W + (TERM? term) + (BIAS? b) )
template <int DIN, int DOUT, int NV, bool ADD_TERM, bool ADD_BIAS, bool RELU>
__global__ void k_proj2(const float* __restrict__ h, const float* __restrict__ W,
                        const float* __restrict__ term, const float* __restrict__ bias,
                        float* __restrict__ out) {
    constexpr int OG = DOUT / 4;
    long long t = (long long)blockIdx.x * blockDim.x + threadIdx.x;
    int oq = (int)(t % OG);
    long long ng = t / OG;
    int n0 = (int)(ng * NV);
    if (n0 >= NN) return;

    float4 acc[NV];
#pragma unroll
    for (int i = 0; i < NV; i++) {
        float4 a = make_float4(0.f, 0.f, 0.f, 0.f);
        if (ADD_BIAS) a = __ldg(reinterpret_cast<const float4*>(bias) + oq);
        if (ADD_TERM) {
            int node = min(n0 + i, NN - 1);
            float4 tv = __ldg(reinterpret_cast<const float4*>(term + (size_t)node * DOUT) + oq);
            a.x += tv.x; a.y += tv.y; a.z += tv.z; a.w += tv.w;
        }
        acc[i] = a;
    }

#pragma unroll
    for (int k = 0; k < DIN; k += 4) {
        float4 w0 = __ldg(reinterpret_cast<const float4*>(W + (size_t)(k + 0) * DOUT) + oq);
        float4 w1 = __ldg(reinterpret_cast<const float4*>(W + (size_t)(k + 1) * DOUT) + oq);
        float4 w2 = __ldg(reinterpret_cast<const float4*>(W + (size_t)(k + 2) * DOUT) + oq);
        float4 w3 = __ldg(reinterpret_cast<const float4*>(W + (size_t)(k + 3) * DOUT) + oq);
#pragma unroll
        for (int i = 0; i < NV; i++) {
            int node = min(n0 + i, NN - 1);
            float4 hv = __ldg(reinterpret_cast<const float4*>(h + (size_t)node * DIN) + (k >> 2));
            acc[i].x = fmaf(hv.x, w0.x, fmaf(hv.y, w1.x, fmaf(hv.z, w2.x, fmaf(hv.w, w3.x, acc[i].x))));
            acc[i].y = fmaf(hv.x, w0.y, fmaf(hv.y, w1.y, fmaf(hv.z, w2.y, fmaf(hv.w, w3.y, acc[i].y))));
            acc[i].z = fmaf(hv.x, w0.z, fmaf(hv.y, w1.z, fmaf(hv.z, w2.z, fmaf(hv.w, w3.z, acc[i].z))));
            acc[i].w = fmaf(hv.x, w0.w, fmaf(hv.y, w1.w, fmaf(hv.z, w2.w, fmaf(hv.w, w3.w, acc[i].w))));
        }
    }

#pragma unroll
    for (int i = 0; i < NV; i++) {
        if (n0 + i < NN) {
            float4 r = acc[i];
            if (RELU) {
                r.x = fmaxf(r.x, 0.f); r.y = fmaxf(r.y, 0.f);
                r.z = fmaxf(r.z, 0.f); r.w = fmaxf(r.w, 0.f);
            }
            reinterpret_cast<float4*>(out + (size_t)(n0 + i) * DOUT)[oq] = r;
        }
    }
}

// Combined z/s projection (layer 2): z = h@Wn ; s = h@Ws + b
template <int DIN, int DOUT, int NV>
__global__ void k_zs(const float* __restrict__ h, const float* __restrict__ Wn,
                     const float* __restrict__ Ws, const float* __restrict__ bias,
                     float* __restrict__ z, float* __restrict__ s) {
    constexpr int OG = DOUT / 4;
    long long t = (long long)blockIdx.x * blockDim.x + threadIdx.x;
    int oq = (int)(t % OG);
    long long ng = t / OG;
    int n0 = (int)(ng * NV);
    if (n0 >= NN) return;

    float4 b4 = __ldg(reinterpret_cast<const float4*>(bias) + oq);
    float4 az[NV], as[NV];
#pragma unroll
    for (int i = 0; i < NV; i++) {
        az[i] = make_float4(0.f, 0.f, 0.f, 0.f);
        as[i] = b4;
    }

#pragma unroll
    for (int k = 0; k < DIN; k += 4) {
        float4 n0w = __ldg(reinterpret_cast<const float4*>(Wn + (size_t)(k + 0) * DOUT) + oq);
        float4 n1w = __ldg(reinterpret_cast<const float4*>(Wn + (size_t)(k + 1) * DOUT) + oq);
        float4 n2w = __ldg(reinterpret_cast<const float4*>(Wn + (size_t)(k + 2) * DOUT) + oq);
        float4 n3w = __ldg(reinterpret_cast<const float4*>(Wn + (size_t)(k + 3) * DOUT) + oq);
        float4 s0w = __ldg(reinterpret_cast<const float4*>(Ws + (size_t)(k + 0) * DOUT) + oq);
        float4 s1w = __ldg(reinterpret_cast<const float4*>(Ws + (size_t)(k + 1) * DOUT) + oq);
        float4 s2w = __ldg(reinterpret_cast<const float4*>(Ws + (size_t)(k + 2) * DOUT) + oq);
        float4 s3w = __ldg(reinterpret_cast<const float4*>(Ws + (size_t)(k + 3) * DOUT) + oq);
#pragma unroll
        for (int i = 0; i < NV; i++) {
            int node = min(n0 + i, NN - 1);
            float4 hv = __ldg(reinterpret_cast<const float4*>(h + (size_t)node * DIN) + (k >> 2));
            az[i].x = fmaf(hv.x, n0w.x, fmaf(hv.y, n1w.x, fmaf(hv.z, n2w.x, fmaf(hv.w, n3w.x, az[i].x))));
            az[i].y = fmaf(hv.x, n0w.y, fmaf(hv.y, n1w.y, fmaf(hv.z, n2w.y, fmaf(hv.w, n3w.y, az[i].y))));
            az[i].z = fmaf(hv.x, n0w.z, fmaf(hv.y, n1w.z, fmaf(hv.z, n2w.z, fmaf(hv.w, n3w.z, az[i].z))));
            az[i].w = fmaf(hv.x, n0w.w, fmaf(hv.y, n1w.w, fmaf(hv.z, n2w.w, fmaf(hv.w, n3w.w, az[i].w))));
            as[i].x = fmaf(hv.x, s0w.x, fmaf(hv.y, s1w.x, fmaf(hv.z, s2w.x, fmaf(hv.w, s3w.x, as[i].x))));
            as[i].y = fmaf(hv.x, s0w.y, fmaf(hv.y, s1w.y, fmaf(hv.z, s2w.y, fmaf(hv.w, s3w.y, as[i].y))));
            as[i].z = fmaf(hv.x, s0w.z, fmaf(hv.y, s1w.z, fmaf(hv.z, s2w.z, fmaf(hv.w, s3w.z, as[i].z))));
            as[i].w = fmaf(hv.x, s0w.w, fmaf(hv.y, s1w.w, fmaf(hv.z, s2w.w, fmaf(hv.w, s3w.w, as[i].w))));
        }
    }

#pragma unroll
    for (int i = 0; i < NV; i++) {
        if (n0 + i < NN) {
            reinterpret_cast<float4*>(z + (size_t)(n0 + i) * DOUT)[oq] = az[i];
            reinterpret_cast<float4*>(s + (size_t)(n0 + i) * DOUT)[oq] = as[i];
        }
    }
}

// scalar combined z/s for DOUT=5 (layer 3)
template <int DIN, int DOUT>
__global__ void k_zsS(const float* __restrict__ h, const float* __restrict__ Wn,
                      const float* __restrict__ Ws, const float* __restrict__ bias,
                      float* __restrict__ z, float* __restrict__ s) {
    long long idx = (long long)blockIdx.x * blockDim.x + threadIdx.x;
    if (idx >= (long long)NN * DOUT) return;
    int v = (int)(idx / DOUT);
    int o = (int)(idx % DOUT);
    const float* hrow = h + (size_t)v * DIN;
    float accz = 0.0f;
    float accs = bias[o];
#pragma unroll
    for (int k = 0; k < DIN; k++) {
        float hv = hrow[k];
        accz = fmaf(hv, Wn[k * DOUT + o], accz);
        accs = fmaf(hv, Ws[k * DOUT + o], accs);
    }
    z[idx] = accz;
    s[idx] = accs;
}

// elementwise combine: out = relu(s + agg), over NN*48
__global__ void k_postE(const float* __restrict__ s, const float* __restrict__ agg,
                        float* __restrict__ out) {
    long long i = (long long)blockIdx.x * blockDim.x + threadIdx.x;
    if (i >= (long long)NN * 12) return;
    float4 sv = reinterpret_cast<const float4*>(s)[i];
    float4 av = reinterpret_cast<const float4*>(agg)[i];
    float4 o = make_float4(fmaxf(sv.x + av.x, 0.f), fmaxf(sv.y + av.y, 0.f),
                           fmaxf(sv.z + av.z, 0.f), fmaxf(sv.w + av.w, 0.f));
    reinterpret_cast<float4*>(out)[i] = o;
}

// ---------------------------------------------------------------------------
// warp-aggregated readout (gid sorted -> warps mostly single-graph)
__global__ void k_readout(const float* __restrict__ h, const int* __restrict__ gid,
                          float* __restrict__ out) {
    int v = blockIdx.x * blockDim.x + threadIdx.x;
    bool ok = (v < NN);
    int g = ok ? gid[v] : -1;
    float c = ok ? 1.0f : 0.0f;
    float f0 = 0, f1 = 0, f2 = 0, f3 = 0, f4 = 0;
    if (ok) {
        const float* hr = h + (size_t)v * 5;
        f0 = hr[0]; f1 = hr[1]; f2 = hr[2]; f3 = hr[3]; f4 = hr[4];
    }
    int g0 = __shfl_sync(0xFFFFFFFFu, ok ? g : __shfl_sync(0xFFFFFFFFu, g, 0), 0);
    bool uniform = __all_sync(0xFFFFFFFFu, !ok || g == g0);
    if (uniform) {
#pragma unroll
        for (int m = 16; m > 0; m >>= 1) {
            c  += __shfl_xor_sync(0xFFFFFFFFu, c, m);
            f0 += __shfl_xor_sync(0xFFFFFFFFu, f0, m);
            f1 += __shfl_xor_sync(0xFFFFFFFFu, f1, m);
            f2 += __shfl_xor_sync(0xFFFFFFFFu, f2, m);
            f3 += __shfl_xor_sync(0xFFFFFFFFu, f3, m);
            f4 += __shfl_xor_sync(0xFFFFFFFFu, f4, m);
        }
        if ((threadIdx.x & 31) == 0 && c > 0.0f) {
            atomicAdd(&g_cnt[g0], c);
            atomicAdd(&out[g0 * 5 + 0], f0);
            atomicAdd(&out[g0 * 5 + 1], f1);
            atomicAdd(&out[g0 * 5 + 2], f2);
            atomicAdd(&out[g0 * 5 + 3], f3);
            atomicAdd(&out[g0 * 5 + 4], f4);
        }
    } else if (ok) {
        atomicAdd(&g_cnt[g], 1.0f);
        atomicAdd(&out[g * 5 + 0], f0);
        atomicAdd(&out[g * 5 + 1], f1);
        atomicAdd(&out[g * 5 + 2], f2);
        atomicAdd(&out[g * 5 + 3], f3);
        atomicAdd(&out[g * 5 + 4], f4);
    }
}

__global__ void k_final(float* __restrict__ out) {
    int i = blockIdx.x * blockDim.x + threadIdx.x;
    if (i < NG * 5) out[i] /= fmaxf(g_cnt[i / 5], 1.0f);
}

// ---------------------------------------------------------------------------
static inline int blks(long long n, int t) { return (int)((n + t - 1) / t); }

extern "C" void kernel_launch(void* const* d_in, const int* in_sizes, int n_in,
                              void* d_out, int out_size) {
    const float* feat = (const float*)d_in[0];
    const int* src = (const int*)d_in[1];
    const int* dst = (const int*)d_in[2];
    const int* gid = (const int*)d_in[3];
    const float* Ws0 = (const float*)d_in[4];
    const float* Wn0 = (const float*)d_in[5];
    const float* b0  = (const float*)d_in[6];
    const float* Ws1 = (const float*)d_in[7];
    const float* Wn1 = (const float*)d_in[8];
    const float* b1  = (const float*)d_in[9];
    const float* Ws2 = (const float*)d_in[10];
    const float* Wn2 = (const float*)d_in[11];
    const float* b2  = (const float*)d_in[12];
    const float* Ws3 = (const float*)d_in[13];
    const float* Wn3 = (const float*)d_in[14];
    const float* b3  = (const float*)d_in[15];
    float* out = (float*)d_out;

    float *bufA, *bufB, *s0buf, *z, *s, *agg, *cnt;
    int *degi;
    cudaGetSymbolAddress((void**)&bufA, g_bufA);
    cudaGetSymbolAddress((void**)&bufB, g_bufB);
    cudaGetSymbolAddress((void**)&s0buf, g_s0);
    cudaGetSymbolAddress((void**)&z, g_z);
    cudaGetSymbolAddress((void**)&s, g_s);
    cudaGetSymbolAddress((void**)&agg, g_agg);
    cudaGetSymbolAddress((void**)&cnt, g_cnt);
    cudaGetSymbolAddress((void**)&degi, g_degi);

    // side stream + events (host-side resources, created once; identical
    // captured work every call)
    static cudaStream_t sB = nullptr;
    static cudaEvent_t evFork0 = nullptr, evS0 = nullptr, evFork1 = nullptr, evS1 = nullptr;
    if (sB == nullptr) {
        cudaStreamCreateWithFlags(&sB, cudaStreamNonBlocking);
        cudaEventCreateWithFlags(&evFork0, cudaEventDisableTiming);
        cudaEventCreateWithFlags(&evS0, cudaEventDisableTiming);
        cudaEventCreateWithFlags(&evFork1, cudaEventDisableTiming);
        cudaEventCreateWithFlags(&evS1, cudaEventDisableTiming);
    }

    const int T = 256;

    // ---- fork: s0 = feat@Ws0 + b0 on side stream, overlapping CSR build ----
    cudaEventRecord(evFork0, 0);
    cudaStreamWaitEvent(sB, evFork0, 0);
    {
        long long th = (long long)((NN + 3) / 4) * 32;
        k_proj2<32, 128, 4, false, true, false><<<blks(th, T), T, 0, sB>>>(
            feat, Ws0, nullptr, b0, s0buf);
    }
    cudaEventRecord(evS0, sB);

    // ---- CSR build (main stream) ----
    cudaMemsetAsync(degi, 0, NN * sizeof(int));
    k_degree<<<blks(NE, T), T>>>(dst);
    k_scan1<<<NB, 1024>>>();
    k_scan2<<<1, 256>>>();
    k_scan3<<<NB, 1024>>>();
    k_build<<<blks(NE, T), T>>>(src, dst);

    // ---- layer 0: gather raw feats, then out0 = relu(s0 + agg@Wn0) ----
    k_gather4<32, 4><<<blks((long long)NN * 32, T), T>>>(feat, agg);
    cudaStreamWaitEvent(0, evS0, 0);
    {
        long long th = (long long)((NN + 3) / 4) * 32;
        k_proj2<32, 128, 4, true, false, true><<<blks(th, T), T>>>(
            agg, Wn0, s0buf, nullptr, bufA);
    }

    // ---- layer 1: z1 on main; s1 on side stream overlapping gather48 ----
    {
        long long th = (long long)((NN + 3) / 4) * 12;
        k_proj2<128, 48, 4, false, false, false><<<blks(th, T), T>>>(
            bufA, Wn1, nullptr, nullptr, z);
    }
    cudaEventRecord(evFork1, 0);
    cudaStreamWaitEvent(sB, evFork1, 0);
    {
        long long th = (long long)((NN + 3) / 4) * 12;
        k_proj2<128, 48, 4, false, true, false><<<blks(th, T), T, 0, sB>>>(
            bufA, Ws1, nullptr, b1, s);
    }
    cudaEventRecord(evS1, sB);
    k_gather4<48, 2><<<blks((long long)NN * 32, T), T>>>(z, agg);
    cudaStreamWaitEvent(0, evS1, 0);
    k_postE<<<blks((long long)NN * 12, T), T>>>(s, agg, bufB);

    // ---- layer 2: 48 -> 28, relu (combined zs + fused gather) ----
    {
        long long th = (long long)((NN + 3) / 4) * 7;
        k_zs<48, 28, 4><<<blks(th, T), T>>>(bufB, Wn2, Ws2, b2, z, s);
    }
    k_gatherF<28, 4, true><<<blks((long long)NN * 32, T), T>>>(z, s, bufA);

    // ---- layer 3: 28 -> 5, linear ----
    k_zsS<28, 5><<<blks((long long)NN * 5, T), T>>>(bufA, Wn3, Ws3, b3, z, s);
    k_gatherF5<<<blks((long long)NN * 32, T), T>>>(z, s, bufB);

    // ---- readout ----
    cudaMemsetAsync(out, 0, NG * 5 * sizeof(float));
    cudaMemsetAsync(cnt, 0, NG * sizeof(float));
    k_readout<<<blks(NN, T), T>>>(bufB, gid, out);
    k_final<<<blks(NG * 5, T), T>>>(out);
}

// round 8
// speedup vs baseline: 1.0152x; 1.0152x over previous
#include <cuda_runtime.h>
#include <cuda_bf16.h>

static const int NN = 200000;
static const int NE = 3200000;
static const int NG = 400;
static const int NB = (NN + 1023) / 1024;  // 196 scan blocks

// Scratch (device globals; no runtime allocation allowed)
__device__ int   g_degi[NN];
__device__ int   g_off[NN + 1];
__device__ int   g_cursor[NN];
__device__ int   g_csr[NE];
__device__ int   g_bsum[256];
__device__ float g_bufA[(size_t)NN * 128];  // layer outputs (max 128)
__device__ float g_bufB[(size_t)NN * 48];
__device__ float g_z[(size_t)NN * 48];      // projected neighbor features
__device__ float g_s[(size_t)NN * 48];      // self-projection + bias
__device__ float g_cnt[NG];

// ---------------------------------------------------------------------------
__global__ void k_degree(const int* __restrict__ dst) {
    int e = blockIdx.x * blockDim.x + threadIdx.x;
    if (e < NE) atomicAdd(&g_degi[dst[e]], 1);
}

// ---- parallel exclusive scan of g_degi -> g_off ----
__global__ void k_scan1() {
    __shared__ int sh[1024];
    int t = threadIdx.x;
    int j = blockIdx.x * 1024 + t;
    sh[t] = (j < NN) ? g_degi[j] : 0;
    __syncthreads();
    for (int d = 512; d > 0; d >>= 1) {
        if (t < d) sh[t] += sh[t + d];
        __syncthreads();
    }
    if (t == 0) g_bsum[blockIdx.x] = sh[0];
}

__global__ void k_scan2() {
    __shared__ int sh[256];
    int t = threadIdx.x;
    int v = (t < NB) ? g_bsum[t] : 0;
    sh[t] = v;
    __syncthreads();
    for (int d = 1; d < 256; d <<= 1) {
        int x = (t >= d) ? sh[t - d] : 0;
        __syncthreads();
        sh[t] += x;
        __syncthreads();
    }
    g_bsum[t] = sh[t] - v;  // exclusive
}

__global__ void k_scan3() {
    __shared__ int sh[1024];
    int t = threadIdx.x;
    int j = blockIdx.x * 1024 + t;
    int v = (j < NN) ? g_degi[j] : 0;
    sh[t] = v;
    __syncthreads();
    for (int d = 1; d < 1024; d <<= 1) {
        int x = (t >= d) ? sh[t - d] : 0;
        __syncthreads();
        sh[t] += x;
        __syncthreads();
    }
    int excl = sh[t] - v + g_bsum[blockIdx.x];
    if (j < NN) {
        g_off[j] = excl;
        g_cursor[j] = excl;
    }
    if (j == NN - 1) g_off[NN] = excl + v;
}

__global__ void k_build(const int* __restrict__ src, const int* __restrict__ dst) {
    int e = blockIdx.x * blockDim.x + threadIdx.x;
    if (e >= NE) return;
    int p = atomicAdd(&g_cursor[dst[e]], 1);
    g_csr[p] = src[e];
}

// ---------------------------------------------------------------------------
__device__ __forceinline__ float f4c(float4 v, int c) {
    return c == 0 ? v.x : (c == 1 ? v.y : (c == 2 ? v.z : v.w));
}

// Fused layer-0: per-warp gather of raw feats (dim 32) + dual projection to 128.
// out[v] = relu( feat[v]@Ws + (mean_nbr feat)@Wn + b ). Warp handles 4 nodes.
__global__ void __launch_bounds__(256) k_sage0F(
    const float* __restrict__ feat, const float* __restrict__ Ws,
    const float* __restrict__ Wn, const float* __restrict__ bias,
    float* __restrict__ out) {
    __shared__ float smWn[32 * 128];
    __shared__ float smWs[32 * 128];
    for (int i = threadIdx.x; i < 32 * 128; i += 256) {
        smWn[i] = Wn[i];
        smWs[i] = Ws[i];
    }
    __syncthreads();

    int gw = (blockIdx.x * blockDim.x + threadIdx.x) >> 5;
    int lane = threadIdx.x & 31;
    int slot = lane >> 3;   // 4 edge slots
    int f4 = lane & 7;      // 8 float4 feature lanes
    int n0 = gw * 4;
    if (n0 >= NN) return;

    // ---- phase A: gather agg for 4 nodes (replicated across lanes) ----
    float4 accA[4];
    float4 fv[4];
#pragma unroll
    for (int i = 0; i < 4; i++) {
        int v = n0 + i;
        float4 acc = make_float4(0.f, 0.f, 0.f, 0.f);
        if (v < NN) {
            int beg = g_off[v];
            int end = g_off[v + 1];
            int e = beg;
            for (; e + 16 <= end; e += 16) {
                int s0 = g_csr[e + slot];
                int s1 = g_csr[e + 4 + slot];
                int s2 = g_csr[e + 8 + slot];
                int s3 = g_csr[e + 12 + slot];
                float4 t0 = __ldg(reinterpret_cast<const float4*>(feat + (size_t)s0 * 32) + f4);
                float4 t1 = __ldg(reinterpret_cast<const float4*>(feat + (size_t)s1 * 32) + f4);
                float4 t2 = __ldg(reinterpret_cast<const float4*>(feat + (size_t)s2 * 32) + f4);
                float4 t3 = __ldg(reinterpret_cast<const float4*>(feat + (size_t)s3 * 32) + f4);
                acc.x += (t0.x + t1.x) + (t2.x + t3.x);
                acc.y += (t0.y + t1.y) + (t2.y + t3.y);
                acc.z += (t0.z + t1.z) + (t2.z + t3.z);
                acc.w += (t0.w + t1.w) + (t2.w + t3.w);
            }
            for (; e < end; e += 4) {
                int myE = e + slot;
                if (myE < end) {
                    int s0 = g_csr[myE];
                    float4 t0 = __ldg(reinterpret_cast<const float4*>(feat + (size_t)s0 * 32) + f4);
                    acc.x += t0.x; acc.y += t0.y; acc.z += t0.z; acc.w += t0.w;
                }
            }
#pragma unroll
            for (int m = 8; m < 32; m <<= 1) {
                acc.x += __shfl_xor_sync(0xFFFFFFFFu, acc.x, m);
                acc.y += __shfl_xor_sync(0xFFFFFFFFu, acc.y, m);
                acc.z += __shfl_xor_sync(0xFFFFFFFFu, acc.z, m);
                acc.w += __shfl_xor_sync(0xFFFFFFFFu, acc.w, m);
            }
            float inv = 1.0f / fmaxf((float)(end - beg), 1.0f);
            acc.x *= inv; acc.y *= inv; acc.z *= inv; acc.w *= inv;
            fv[i] = __ldg(reinterpret_cast<const float4*>(feat + (size_t)v * 32) + f4);
        } else {
            fv[i] = make_float4(0.f, 0.f, 0.f, 0.f);
        }
        accA[i] = acc;
    }

    // ---- phase B: project. Lane owns output cols [lane*4, lane*4+4). ----
    float4 b4 = __ldg(reinterpret_cast<const float4*>(bias) + lane);
    float4 o[4];
#pragma unroll
    for (int i = 0; i < 4; i++) o[i] = b4;

#pragma unroll
    for (int k = 0; k < 32; k++) {
        float4 wn4 = reinterpret_cast<const float4*>(smWn)[k * 32 + lane];
        float4 ws4 = reinterpret_cast<const float4*>(smWs)[k * 32 + lane];
        const int srcl = k >> 2;
        const int comp = k & 3;
#pragma unroll
        for (int i = 0; i < 4; i++) {
            float a = __shfl_sync(0xFFFFFFFFu, f4c(accA[i], comp), srcl);
            float f = __shfl_sync(0xFFFFFFFFu, f4c(fv[i], comp), srcl);
            o[i].x = fmaf(a, wn4.x, fmaf(f, ws4.x, o[i].x));
            o[i].y = fmaf(a, wn4.y, fmaf(f, ws4.y, o[i].y));
            o[i].z = fmaf(a, wn4.z, fmaf(f, ws4.z, o[i].z));
            o[i].w = fmaf(a, wn4.w, fmaf(f, ws4.w, o[i].w));
        }
    }

#pragma unroll
    for (int i = 0; i < 4; i++) {
        int v = n0 + i;
        if (v < NN) {
            float4 r = make_float4(fmaxf(o[i].x, 0.f), fmaxf(o[i].y, 0.f),
                                   fmaxf(o[i].z, 0.f), fmaxf(o[i].w, 0.f));
            reinterpret_cast<float4*>(out + (size_t)v * 128)[lane] = r;
        }
    }
}

// ---------------------------------------------------------------------------
// fused gather (layers 1,2): out[v] = act( s[v] + sum z[nbr]/max(deg,1) )
template <int DIM, int SLOTS, bool RELU>
__global__ void k_gatherF(const float* __restrict__ z, const float* __restrict__ s,
                          float* __restrict__ out) {
    constexpr int F4L = 32 / SLOTS;
    constexpr int NF4 = DIM / 4;
    int gt = blockIdx.x * blockDim.x + threadIdx.x;
    int v = gt >> 5;
    if (v >= NN) return;
    int lane = gt & 31;
    int slot = lane / F4L;
    int f4 = lane % F4L;
    bool act = (f4 < NF4);

    int beg = g_off[v];
    int end = g_off[v + 1];
    float4 acc = make_float4(0.f, 0.f, 0.f, 0.f);

    int e = beg;
    for (; e + 4 * SLOTS <= end; e += 4 * SLOTS) {
        int s0 = g_csr[e + slot];
        int s1 = g_csr[e + SLOTS + slot];
        int s2 = g_csr[e + 2 * SLOTS + slot];
        int s3 = g_csr[e + 3 * SLOTS + slot];
        if (act) {
            float4 t0 = __ldg(reinterpret_cast<const float4*>(z + (size_t)s0 * DIM) + f4);
            float4 t1 = __ldg(reinterpret_cast<const float4*>(z + (size_t)s1 * DIM) + f4);
            float4 t2 = __ldg(reinterpret_cast<const float4*>(z + (size_t)s2 * DIM) + f4);
            float4 t3 = __ldg(reinterpret_cast<const float4*>(z + (size_t)s3 * DIM) + f4);
            acc.x += (t0.x + t1.x) + (t2.x + t3.x);
            acc.y += (t0.y + t1.y) + (t2.y + t3.y);
            acc.z += (t0.z + t1.z) + (t2.z + t3.z);
            acc.w += (t0.w + t1.w) + (t2.w + t3.w);
        }
    }
    for (; e < end; e += SLOTS) {
        int myE = e + slot;
        if (myE < end && act) {
            int s0 = g_csr[myE];
            float4 t0 = __ldg(reinterpret_cast<const float4*>(z + (size_t)s0 * DIM) + f4);
            acc.x += t0.x; acc.y += t0.y; acc.z += t0.z; acc.w += t0.w;
        }
    }
#pragma unroll
    for (int m = F4L; m < 32; m <<= 1) {
        acc.x += __shfl_xor_sync(0xFFFFFFFFu, acc.x, m);
        acc.y += __shfl_xor_sync(0xFFFFFFFFu, acc.y, m);
        acc.z += __shfl_xor_sync(0xFFFFFFFFu, acc.z, m);
        acc.w += __shfl_xor_sync(0xFFFFFFFFu, acc.w, m);
    }
    float inv = 1.0f / fmaxf((float)(end - beg), 1.0f);
    if (slot == 0 && act) {
        float4 sv = __ldg(reinterpret_cast<const float4*>(s + (size_t)v * DIM) + f4);
        float4 o = make_float4(sv.x + acc.x * inv, sv.y + acc.y * inv,
                               sv.z + acc.z * inv, sv.w + acc.w * inv);
        if (RELU) {
            o.x = fmaxf(o.x, 0.f); o.y = fmaxf(o.y, 0.f);
            o.z = fmaxf(o.z, 0.f); o.w = fmaxf(o.w, 0.f);
        }
        reinterpret_cast<float4*>(out + (size_t)v * DIM)[f4] = o;
    }
}

// fused scalar gather for DIM=5 (layer 3, no relu)
__global__ void k_gatherF5(const float* __restrict__ z, const float* __restrict__ s,
                           float* __restrict__ out) {
    constexpr int DIM = 5;
    int gt = blockIdx.x * blockDim.x + threadIdx.x;
    int v = gt >> 5;
    if (v >= NN) return;
    int lane = gt & 31;
    int slot = lane >> 3;
    int f = lane & 7;
    bool act = (f < DIM);

    int beg = g_off[v];
    int end = g_off[v + 1];
    float acc = 0.0f;
    int e = beg;
    for (; e + 8 <= end; e += 8) {
        int s0 = g_csr[e + slot];
        int s1 = g_csr[e + 4 + slot];
        if (act) acc += z[(size_t)s0 * DIM + f] + z[(size_t)s1 * DIM + f];
    }
    for (; e < end; e += 4) {
        int myE = e + slot;
        if (myE < end && act) acc += z[(size_t)g_csr[myE] * DIM + f];
    }
#pragma unroll
    for (int m = 8; m < 32; m <<= 1) acc += __shfl_xor_sync(0xFFFFFFFFu, acc, m);
    float inv = 1.0f / fmaxf((float)(end - beg), 1.0f);
    if (slot == 0 && act)
        out[(size_t)v * DIM + f] = s[(size_t)v * DIM + f] + acc * inv;
}

// ---------------------------------------------------------------------------
// Combined z/s projection: z = h@Wn ; s = h@Ws + b. Thread -> float4 x NV nodes.
template <int DIN, int DOUT, int NV>
__global__ void k_zs(const float* __restrict__ h, const float* __restrict__ Wn,
                     const float* __restrict__ Ws, const float* __restrict__ bias,
                     float* __restrict__ z, float* __restrict__ s) {
    constexpr int OG = DOUT / 4;
    long long t = (long long)blockIdx.x * blockDim.x + threadIdx.x;
    int oq = (int)(t % OG);
    long long ng = t / OG;
    int n0 = (int)(ng * NV);
    if (n0 >= NN) return;

    float4 b4 = __ldg(reinterpret_cast<const float4*>(bias) + oq);
    float4 az[NV], as[NV];
#pragma unroll
    for (int i = 0; i < NV; i++) {
        az[i] = make_float4(0.f, 0.f, 0.f, 0.f);
        as[i] = b4;
    }

#pragma unroll
    for (int k = 0; k < DIN; k += 4) {
        float4 n0w = __ldg(reinterpret_cast<const float4*>(Wn + (size_t)(k + 0) * DOUT) + oq);
        float4 n1w = __ldg(reinterpret_cast<const float4*>(Wn + (size_t)(k + 1) * DOUT) + oq);
        float4 n2w = __ldg(reinterpret_cast<const float4*>(Wn + (size_t)(k + 2) * DOUT) + oq);
        float4 n3w = __ldg(reinterpret_cast<const float4*>(Wn + (size_t)(k + 3) * DOUT) + oq);
        float4 s0w = __ldg(reinterpret_cast<const float4*>(Ws + (size_t)(k + 0) * DOUT) + oq);
        float4 s1w = __ldg(reinterpret_cast<const float4*>(Ws + (size_t)(k + 1) * DOUT) + oq);
        float4 s2w = __ldg(reinterpret_cast<const float4*>(Ws + (size_t)(k + 2) * DOUT) + oq);
        float4 s3w = __ldg(reinterpret_cast<const float4*>(Ws + (size_t)(k + 3) * DOUT) + oq);
#pragma unroll
        for (int i = 0; i < NV; i++) {
            int node = min(n0 + i, NN - 1);
            float4 hv = __ldg(reinterpret_cast<const float4*>(h + (size_t)node * DIN) + (k >> 2));
            az[i].x = fmaf(hv.x, n0w.x, fmaf(hv.y, n1w.x, fmaf(hv.z, n2w.x, fmaf(hv.w, n3w.x, az[i].x))));
            az[i].y = fmaf(hv.x, n0w.y, fmaf(hv.y, n1w.y, fmaf(hv.z, n2w.y, fmaf(hv.w, n3w.y, az[i].y))));
            az[i].z = fmaf(hv.x, n0w.z, fmaf(hv.y, n1w.z, fmaf(hv.z, n2w.z, fmaf(hv.w, n3w.z, az[i].z))));
            az[i].w = fmaf(hv.x, n0w.w, fmaf(hv.y, n1w.w, fmaf(hv.z, n2w.w, fmaf(hv.w, n3w.w, az[i].w))));
            as[i].x = fmaf(hv.x, s0w.x, fmaf(hv.y, s1w.x, fmaf(hv.z, s2w.x, fmaf(hv.w, s3w.x, as[i].x))));
            as[i].y = fmaf(hv.x, s0w.y, fmaf(hv.y, s1w.y, fmaf(hv.z, s2w.y, fmaf(hv.w, s3w.y, as[i].y))));
            as[i].z = fmaf(hv.x, s0w.z, fmaf(hv.y, s1w.z, fmaf(hv.z, s2w.z, fmaf(hv.w, s3w.z, as[i].z))));
            as[i].w = fmaf(hv.x, s0w.w, fmaf(hv.y, s1w.w, fmaf(hv.z, s2w.w, fmaf(hv.w, s3w.w, as[i].w))));
        }
    }

#pragma unroll
    for (int i = 0; i < NV; i++) {
        if (n0 + i < NN) {
            reinterpret_cast<float4*>(z + (size_t)(n0 + i) * DOUT)[oq] = az[i];
            reinterpret_cast<float4*>(s + (size_t)(n0 + i) * DOUT)[oq] = as[i];
        }
    }
}

// scalar combined z/s for DOUT=5 (layer 3)
template <int DIN, int DOUT>
__global__ void k_zsS(const float* __restrict__ h, const float* __restrict__ Wn,
                      const float* __restrict__ Ws, const float* __restrict__ bias,
                      float* __restrict__ z, float* __restrict__ s) {
    long long idx = (long long)blockIdx.x * blockDim.x + threadIdx.x;
    if (idx >= (long long)NN * DOUT) return;
    int v = (int)(idx / DOUT);
    int o = (int)(idx % DOUT);
    const float* hrow = h + (size_t)v * DIN;
    float accz = 0.0f;
    float accs = bias[o];
#pragma unroll
    for (int k = 0; k < DIN; k++) {
        float hv = hrow[k];
        accz = fmaf(hv, Wn[k * DOUT + o], accz);
        accs = fmaf(hv, Ws[k * DOUT + o], accs);
    }
    z[idx] = accz;
    s[idx] = accs;
}

// ---------------------------------------------------------------------------
// warp-aggregated readout (gid sorted -> warps mostly single-graph)
__global__ void k_readout(const float* __restrict__ h, const int* __restrict__ gid,
                          float* __restrict__ out) {
    int v = blockIdx.x * blockDim.x + threadIdx.x;
    bool ok = (v < NN);
    int g = ok ? gid[v] : -1;
    float c = ok ? 1.0f : 0.0f;
    float f0 = 0, f1 = 0, f2 = 0, f3 = 0, f4 = 0;
    if (ok) {
        const float* hr = h + (size_t)v * 5;
        f0 = hr[0]; f1 = hr[1]; f2 = hr[2]; f3 = hr[3]; f4 = hr[4];
    }
    int g0 = __shfl_sync(0xFFFFFFFFu, ok ? g : __shfl_sync(0xFFFFFFFFu, g, 0), 0);
    bool uniform = __all_sync(0xFFFFFFFFu, !ok || g == g0);
    if (uniform) {
#pragma unroll
        for (int m = 16; m > 0; m >>= 1) {
            c  += __shfl_xor_sync(0xFFFFFFFFu, c, m);
            f0 += __shfl_xor_sync(0xFFFFFFFFu, f0, m);
            f1 += __shfl_xor_sync(0xFFFFFFFFu, f1, m);
            f2 += __shfl_xor_sync(0xFFFFFFFFu, f2, m);
            f3 += __shfl_xor_sync(0xFFFFFFFFu, f3, m);
            f4 += __shfl_xor_sync(0xFFFFFFFFu, f4, m);
        }
        if ((threadIdx.x & 31) == 0 && c > 0.0f) {
            atomicAdd(&g_cnt[g0], c);
            atomicAdd(&out[g0 * 5 + 0], f0);
            atomicAdd(&out[g0 * 5 + 1], f1);
            atomicAdd(&out[g0 * 5 + 2], f2);
            atomicAdd(&out[g0 * 5 + 3], f3);
            atomicAdd(&out[g0 * 5 + 4], f4);
        }
    } else if (ok) {
        atomicAdd(&g_cnt[g], 1.0f);
        atomicAdd(&out[g * 5 + 0], f0);
        atomicAdd(&out[g * 5 + 1], f1);
        atomicAdd(&out[g * 5 + 2], f2);
        atomicAdd(&out[g * 5 + 3], f3);
        atomicAdd(&out[g * 5 + 4], f4);
    }
}

__global__ void k_final(float* __restrict__ out) {
    int i = blockIdx.x * blockDim.x + threadIdx.x;
    if (i < NG * 5) out[i] /= fmaxf(g_cnt[i / 5], 1.0f);
}

// ---------------------------------------------------------------------------
static inline int blks(long long n, int t) { return (int)((n + t - 1) / t); }

extern "C" void kernel_launch(void* const* d_in, const int* in_sizes, int n_in,
                              void* d_out, int out_size) {
    const float* feat = (const float*)d_in[0];
    const int* src = (const int*)d_in[1];
    const int* dst = (const int*)d_in[2];
    const int* gid = (const int*)d_in[3];
    const float* Ws0 = (const float*)d_in[4];
    const float* Wn0 = (const float*)d_in[5];
    const float* b0  = (const float*)d_in[6];
    const float* Ws1 = (const float*)d_in[7];
    const float* Wn1 = (const float*)d_in[8];
    const float* b1  = (const float*)d_in[9];
    const float* Ws2 = (const float*)d_in[10];
    const float* Wn2 = (const float*)d_in[11];
    const float* b2  = (const float*)d_in[12];
    const float* Ws3 = (const float*)d_in[13];
    const float* Wn3 = (const float*)d_in[14];
    const float* b3  = (const float*)d_in[15];
    float* out = (float*)d_out;

    float *bufA, *bufB, *z, *s, *cnt;
    int *degi;
    cudaGetSymbolAddress((void**)&bufA, g_bufA);
    cudaGetSymbolAddress((void**)&bufB, g_bufB);
    cudaGetSymbolAddress((void**)&z, g_z);
    cudaGetSymbolAddress((void**)&s, g_s);
    cudaGetSymbolAddress((void**)&cnt, g_cnt);
    cudaGetSymbolAddress((void**)&degi, g_degi);

    const int T = 256;

    // ---- CSR build ----
    cudaMemsetAsync(degi, 0, NN * sizeof(int));
    k_degree<<<blks(NE, T), T>>>(dst);
    k_scan1<<<NB, 1024>>>();
    k_scan2<<<1, 256>>>();
    k_scan3<<<NB, 1024>>>();
    k_build<<<blks(NE, T), T>>>(src, dst);

    // ---- layer 0: fused gather + dual projection (32 -> 128, relu) ----
    {
        long long th = (long long)((NN + 3) / 4) * 32;
        k_sage0F<<<blks(th, T), T>>>(feat, Ws0, Wn0, b0, bufA);
    }

    // ---- layer 1: 128 -> 48, relu (combined zs + fused gather) ----
    {
        long long th = (long long)((NN + 3) / 4) * 12;
        k_zs<128, 48, 4><<<blks(th, T), T>>>(bufA, Wn1, Ws1, b1, z, s);
    }
    k_gatherF<48, 2, true><<<blks((long long)NN * 32, T), T>>>(z, s, bufB);

    // ---- layer 2: 48 -> 28, relu ----
    {
        long long th = (long long)((NN + 3) / 4) * 7;
        k_zs<48, 28, 4><<<blks(th, T), T>>>(bufB, Wn2, Ws2, b2, z, s);
    }
    k_gatherF<28, 4, true><<<blks((long long)NN * 32, T), T>>>(z, s, bufA);

    // ---- layer 3: 28 -> 5, linear ----
    k_zsS<28, 5><<<blks((long long)NN * 5, T), T>>>(bufA, Wn3, Ws3, b3, z, s);
    k_gatherF5<<<blks((long long)NN * 32, T), T>>>(z, s, bufB);

    // ---- readout ----
    cudaMemsetAsync(out, 0, NG * 5 * sizeof(float));
    cudaMemsetAsync(cnt, 0, NG * sizeof(float));
    k_readout<<<blks(NN, T), T>>>(bufB, gid, out);
    k_final<<<blks(NG * 5, T), T>>>(out);
}